// round 17
// baseline (speedup 1.0000x reference)
#include <cuda_runtime.h>
#include <cuda_bf16.h>
#include <math_constants.h>

#define H_OUT  135
#define W_OUT  240
#define NPIX   (H_OUT * W_OUT)   // 32400
#define EPS_A  1e-8f
#define Z_CLIP 0.01f

#define MAXF   4096
#define NSPLIT 64
#define FLEN_MAX 32              // faces per split (F=2048 -> flen=32)

// Warp tile: 32 rows (lane) x 8 cols (k)
#define TROWS 32
#define TCOLS 8
#define NTR   ((H_OUT + TROWS - 1) / TROWS)   // 5
#define NTC   (W_OUT / TCOLS)                 // 30
#define NTILES (NTR * NTC)                    // 150
#define WPB   8
#define NBLKX ((NTILES + WPB - 1) / WPB)      // 19
#define BLOCK (32 * WPB)                      // 256

// Per-face folded coefficients, 3 x float4 (global copy, for finalize):
//  C0 = (gx0, gy0, k0, gx1)
//  C1 = (gy1, k1, gx2, gy2)
//  C2 = (k2,  zx,  zy,  zk)
// b_i = gx_i*px + gy_i*py + k_i ;  zp = zx*px + zy*py + zk
__device__ float4 g_c[MAXF * 3];
// packed ((0xFFFFFFFF - z_bits) << 32) | (0xFFFFFFFF - face); 0 == empty.
// Zero-initialized at module load; finalize resets to 0 every call,
// so every graph replay starts from identical state.
__device__ unsigned long long g_pk[NPIX];

__device__ __forceinline__ void project_v(float vx, float vy, float vz,
                                          float& xn, float& yn) {
    float xs = 1000.0f * (-vx) / vz + 960.0f;
    float ys = 1000.0f * vy    / vz + 540.0f;
    xn = -(2.0f * xs - 1920.0f) / 1080.0f;
    yn = -(2.0f * ys - 1080.0f) / 1080.0f;
}

__device__ __forceinline__ float pix_x(int c) {
    return -(2.0f * (float)c + 1.0f - (float)W_OUT) / 135.0f;
}
__device__ __forceinline__ float pix_y(int r_out) {
    int h = H_OUT - 1 - r_out;   // undo the [::-1] row flip
    return -(2.0f * (float)h + 1.0f - (float)H_OUT) / 135.0f;
}

// a*b - c*d with two-prod compensation (~0.5 ulp)
__device__ __forceinline__ float cross_acc(float a, float b, float c, float d) {
    float p1 = a * b;
    float e1 = fmaf(a, b, -p1);
    float p2 = c * d;
    float e2 = fmaf(c, d, -p2);
    return (p1 - p2) + (e1 - e2);
}

// a0*b0 + a1*b1 + a2*b2 with two-prod + two-sum compensation
__device__ __forceinline__ float dot3_acc(float a0, float b0,
                                          float a1, float b1,
                                          float a2, float b2) {
    float p0 = a0 * b0, e0 = fmaf(a0, b0, -p0);
    float p1 = a1 * b1, e1 = fmaf(a1, b1, -p1);
    float p2 = a2 * b2, e2 = fmaf(a2, b2, -p2);
    float s1 = p0 + p1;
    float v1 = s1 - p0;
    float t1 = (p0 - (s1 - v1)) + (p1 - v1);
    float s2 = s1 + p2;
    float v2 = s2 - s1;
    float t2 = (s1 - (s2 - v2)) + (p2 - v2);
    return s2 + (t1 + t2 + e0 + e1 + e2);
}

__global__ __launch_bounds__(BLOCK)
void raster_fused_kernel(const float* __restrict__ verts,
                         const int*   __restrict__ faces,
                         int F, int flen) {
    __shared__ float4 sc[FLEN_MAX * 3];
    __shared__ float4 sbb[FLEN_MAX];
    __shared__ int    slist[WPB][FLEN_MAX];

    int s    = blockIdx.y;
    int fbeg = s * flen;
    int n    = F - fbeg;
    if (n > flen) n = flen;
    if (n < 0) n = 0;

    // ---- in-block face setup: one face per thread (flen <= BLOCK), fp32 ----
    int fl = threadIdx.x;                  // local face index
    if (fl < n) {
        int f = fbeg + fl;
        int i0 = faces[3 * f + 0];
        int i1 = faces[3 * f + 1];
        int i2 = faces[3 * f + 2];

        float v0z = verts[3 * i0 + 2];
        float v1z = verts[3 * i1 + 2];
        float v2z = verts[3 * i2 + 2];

        float x0, y0, x1, y1, x2, y2;
        project_v(verts[3 * i0], verts[3 * i0 + 1], v0z, x0, y0);
        project_v(verts[3 * i1], verts[3 * i1 + 1], v1z, x1, y1);
        project_v(verts[3 * i2], verts[3 * i2 + 1], v2z, x2, y2);

        float area = (x1 - x0) * (y2 - y0) - (y1 - y0) * (x2 - x0);
        bool ok = (fabsf(area) > EPS_A) &&
                  (v0z > Z_CLIP) && (v1z > Z_CLIP) && (v2z > Z_CLIP);

        float4 C0, C1, C2, BB;
        if (ok) {
            float inv = 1.0f / area;          // fp32 reciprocal, same as reference
            float dy21 = y2 - y1, dx21 = x2 - x1;
            float dy02 = y0 - y2, dx02 = x0 - x2;
            float dy10 = y1 - y0, dx10 = x1 - x0;

            float gx0 = -dy21 * inv;
            float gy0 =  dx21 * inv;
            float k0  = cross_acc(dy21, x1, dx21, y1) * inv;
            float gx1 = -dy02 * inv;
            float gy1 =  dx02 * inv;
            float k1  = cross_acc(dy02, x2, dx02, y2) * inv;
            float gx2 = -dy10 * inv;
            float gy2 =  dx10 * inv;
            float k2  = cross_acc(dy10, x0, dx10, y0) * inv;

            float zx = dot3_acc(gx0, v0z, gx1, v1z, gx2, v2z);
            float zy = dot3_acc(gy0, v0z, gy1, v1z, gy2, v2z);
            float zk = dot3_acc(k0,  v0z, k1,  v1z, k2,  v2z);

            C0 = make_float4(gx0, gy0, k0, gx1);
            C1 = make_float4(gy1, k1, gx2, gy2);
            C2 = make_float4(k2, zx, zy, zk);
            float m = 2e-6f;
            BB = make_float4(fminf(x0, fminf(x1, x2)) - m,
                             fmaxf(x0, fmaxf(x1, x2)) + m,
                             fminf(y0, fminf(y1, y2)) - m,
                             fmaxf(y0, fmaxf(y1, y2)) + m);
        } else {
            C0 = make_float4(0.0f, 0.0f, -1.0f, 0.0f);
            C1 = make_float4(0.0f, 0.0f, 0.0f, 0.0f);
            C2 = make_float4(0.0f, 0.0f, 0.0f, 0.0f);
            BB = make_float4(CUDART_INF_F, -CUDART_INF_F,
                             CUDART_INF_F, -CUDART_INF_F);   // never passes cull
        }

        sc[fl * 3 + 0] = C0;
        sc[fl * 3 + 1] = C1;
        sc[fl * 3 + 2] = C2;
        sbb[fl] = BB;

        if (blockIdx.x == 0) {            // one block per split publishes for finalize
            g_c[f * 3 + 0] = C0;
            g_c[f * 3 + 1] = C1;
            g_c[f * 3 + 2] = C2;
        }
    }
    __syncthreads();

    // ---- raster ----
    int wid  = threadIdx.x >> 5;
    int lane = threadIdx.x & 31;
    // block-adjacent tiles
    int t    = blockIdx.x * WPB + wid;
    if (t >= NTILES) return;

    int tr = t / NTC;
    int tc = t - tr * NTC;
    int r0 = tr * TROWS;
    int r1 = min(r0 + TROWS - 1, H_OUT - 1);
    int c0 = tc * TCOLS;

    int  row   = r0 + lane;
    bool rowok = (row < H_OUT);
    float py   = pix_y(rowok ? row : (H_OUT - 1));

    // warp-uniform tile bounds (px decreases with c, py increases with r_out)
    float pyl = pix_y(r0);
    float pyh = pix_y(r1);
    float pxh = pix_x(c0);
    float pxl = pix_x(c0 + TCOLS - 1);

    // cull -> compacted ascending face list (per warp)
    int nlist = 0;
    for (int g = 0; g < n; g += 32) {
        int f = g + lane;
        bool pass = false;
        if (f < n) {
            float4 bb = sbb[f];
            pass = (bb.y >= pxl) & (bb.x <= pxh) & (bb.w >= pyl) & (bb.z <= pyh);
        }
        unsigned m = __ballot_sync(0xffffffffu, pass);
        if (pass) slist[wid][nlist + __popc(m & ((1u << lane) - 1u))] = f;
        nlist += __popc(m);
    }

    float px[TCOLS], z[TCOLS];
    int fb[TCOLS];
    #pragma unroll
    for (int k = 0; k < TCOLS; k++) {
        px[k] = pix_x(c0 + k);
        z[k]  = CUDART_INF_F;
        fb[k] = -1;
    }

    for (int j = 0; j < nlist; j++) {
        int f = slist[wid][j];
        float4 A = sc[f * 3 + 0];
        float4 B = sc[f * 3 + 1];
        float4 C = sc[f * 3 + 2];

        // per-lane (py) terms, shared across the 8 columns
        float t0 = fmaf(A.y, py, A.z);   // gy0*py + k0
        float t1 = fmaf(B.x, py, B.y);   // gy1*py + k1
        float t2 = fmaf(B.w, py, C.x);   // gy2*py + k2
        float tz = fmaf(C.z, py, C.w);   // zy*py + zk
        int   gf = fbeg + f;

        #pragma unroll
        for (int k = 0; k < TCOLS; k++) {
            float b0 = fmaf(A.x, px[k], t0);
            float b1 = fmaf(A.w, px[k], t1);
            float b2 = fmaf(B.z, px[k], t2);
            float zp = fmaf(C.y, px[k], tz);
            float mm = fminf(fminf(b0, b1), b2);
            float zc = (mm >= 0.0f) ? zp : CUDART_INF_F;
            if (zc < z[k]) { z[k] = zc; fb[k] = gf; }
        }
    }

    if (rowok) {
        int pbase = row * W_OUT + c0;
        #pragma unroll
        for (int k = 0; k < TCOLS; k++) {
            if (fb[k] >= 0) {
                // inverted key: max over key == min z, tie -> min face index
                unsigned long long key =
                    ((unsigned long long)(0xFFFFFFFFu - __float_as_uint(z[k])) << 32) |
                    (unsigned long long)(0xFFFFFFFFu - (unsigned)fb[k]);
                atomicMax(&g_pk[pbase + k], key);
            }
        }
    }
}

__global__ __launch_bounds__(256)
void finalize_kernel(float* __restrict__ out) {
    int p = blockIdx.x * 256 + threadIdx.x;
    if (p >= NPIX) return;

    unsigned long long key = g_pk[p];
    g_pk[p] = 0ull;   // restore pristine state for the next graph replay

    int fbv = -1;
    float bb0 = -1.0f, bb1 = -1.0f, bb2 = -1.0f;

    if (key != 0ull) {
        fbv = (int)(0xFFFFFFFFu - (unsigned)(key & 0xFFFFFFFFull));
        float4 A = g_c[fbv * 3 + 0];
        float4 B = g_c[fbv * 3 + 1];
        float k2 = g_c[fbv * 3 + 2].x;

        int row = p / W_OUT;
        int c   = p - row * W_OUT;
        float py = pix_y(row);
        float px = pix_x(c);

        // identical op order to the raster loop -> identical values
        float t0 = fmaf(A.y, py, A.z);
        float t1 = fmaf(B.x, py, B.y);
        float t2 = fmaf(B.w, py, k2);
        bb0 = fmaf(A.x, px, t0);
        bb1 = fmaf(A.w, px, t1);
        bb2 = fmaf(B.z, px, t2);
    }

    out[p] = (float)fbv;
    float* bary = out + NPIX + 3 * p;
    bary[0] = bb0;
    bary[1] = bb1;
    bary[2] = bb2;
}

extern "C" void kernel_launch(void* const* d_in, const int* in_sizes, int n_in,
                              void* d_out, int out_size) {
    const float* verts = (const float*)d_in[0];
    const int*   faces = (const int*)d_in[1];
    int F = in_sizes[1] / 3;
    if (F > MAXF) F = MAXF;

    int flen = (F + NSPLIT - 1) / NSPLIT;
    if (flen > FLEN_MAX) flen = FLEN_MAX;      // 1-face-per-thread invariant
    if (flen < 1) flen = 1;
    int nsplit = (F + flen - 1) / flen;
    if (nsplit < 1) nsplit = 1;

    raster_fused_kernel<<<dim3(NBLKX, nsplit), BLOCK>>>(verts, faces, F, flen);
    finalize_kernel<<<(NPIX + 255) / 256, 256>>>((float*)d_out);
}